// round 1
// baseline (speedup 1.0000x reference)
#include <cuda_runtime.h>

namespace {
constexpr int B = 8;
constexpr int N = 2048;
constexpr int D = 128;
constexpr float NEGV = -9.0e15f;
}

// Scratch (static device globals; no runtime allocation).
__device__ float g_Wt[D * D];                 // W^T
__device__ float g_h[B * N * D];              // h = xW^T + b
__device__ float g_hA[B * N * D];             // hA = h A
__device__ float g_hp[B * N * D];             // relu(att @ h)
__device__ float g_E[(size_t)B * N * N];      // E = hA h^T
__device__ float g_T[(size_t)B * N * N];      // masked transposed logits -> probs

// ---------------------------------------------------------------------------
// 128x128 transpose of W_w (once, tiny).
__global__ void transpose_k(const float* __restrict__ W, float* __restrict__ Wt) {
    __shared__ float t[32][33];
    const int bx = blockIdx.x, by = blockIdx.y;
    const int x = bx * 32 + threadIdx.x;
    const int y0 = by * 32;
    for (int i = threadIdx.y; i < 32; i += 8)
        t[i][threadIdx.x] = W[(y0 + i) * D + x];
    __syncthreads();
    const int xo = by * 32 + threadIdx.x;
    const int yo0 = bx * 32;
    for (int i = threadIdx.y; i < 32; i += 8)
        Wt[(yo0 + i) * D + xo] = t[threadIdx.x][i];
}

// ---------------------------------------------------------------------------
// C[r][c] = sum_k X[r][k] * M[k][c] (+ bias[c]).  X: [B*N, D], M: [D, D].
// Block: 32 rows x 128 cols, 256 threads, K-step 32.
__global__ void __launch_bounds__(256) gemm_rows_k(
    const float* __restrict__ X, const float* __restrict__ M,
    const float* __restrict__ bias, float* __restrict__ C) {
    __shared__ float sM[32][D + 1];
    __shared__ float sX[32][33];
    const int row0 = blockIdx.x * 32;
    const int tid = threadIdx.x;
    const int tc = tid & 15;
    const int tr = tid >> 4;
    float acc[2][8];
#pragma unroll
    for (int a = 0; a < 2; a++)
#pragma unroll
        for (int c = 0; c < 8; c++) acc[a][c] = 0.0f;

    for (int k0 = 0; k0 < D; k0 += 32) {
#pragma unroll
        for (int i = tid; i < 32 * D; i += 256) {
            int kk = i >> 7, cc = i & 127;
            sM[kk][cc] = M[(k0 + kk) * D + cc];
        }
#pragma unroll
        for (int i = tid; i < 32 * 32; i += 256) {
            int r = i >> 5, kk = i & 31;
            sX[r][kk] = X[(size_t)(row0 + r) * D + k0 + kk];
        }
        __syncthreads();
#pragma unroll 8
        for (int kk = 0; kk < 32; kk++) {
            float x0 = sX[tr][kk];
            float x1 = sX[tr + 16][kk];
#pragma unroll
            for (int c = 0; c < 8; c++) {
                float mv = sM[kk][tc + c * 16];
                acc[0][c] += x0 * mv;
                acc[1][c] += x1 * mv;
            }
        }
        __syncthreads();
    }
#pragma unroll
    for (int a = 0; a < 2; a++) {
        int r = row0 + tr + a * 16;
#pragma unroll
        for (int c = 0; c < 8; c++) {
            int col = tc + c * 16;
            float v = acc[a][c];
            if (bias) v += bias[col];
            C[(size_t)r * D + col] = v;
        }
    }
}

// ---------------------------------------------------------------------------
// E[b][j][k] = sum_l hA[b][j][l] * h[b][k][l].  Tile 128(j) x 64(k), K-step 32.
__global__ void __launch_bounds__(256) e_gemm_k(
    const float* __restrict__ hA, const float* __restrict__ h,
    float* __restrict__ E) {
    __shared__ float sA[128][33];
    __shared__ float sB[64][33];
    const int b = blockIdx.z;
    const int j0 = blockIdx.y * 128;
    const int k0 = blockIdx.x * 64;
    const int tid = threadIdx.x;
    const int tj = tid >> 4, tk = tid & 15;
    const float* Ab = hA + (size_t)b * N * D;
    const float* Hb = h + (size_t)b * N * D;
    float acc[8][4];
#pragma unroll
    for (int a = 0; a < 8; a++)
#pragma unroll
        for (int c = 0; c < 4; c++) acc[a][c] = 0.0f;

    for (int l0 = 0; l0 < D; l0 += 32) {
#pragma unroll
        for (int i = tid; i < 128 * 32; i += 256) {
            int r = i >> 5, ll = i & 31;
            sA[r][ll] = Ab[(size_t)(j0 + r) * D + l0 + ll];
        }
#pragma unroll
        for (int i = tid; i < 64 * 32; i += 256) {
            int r = i >> 5, ll = i & 31;
            sB[r][ll] = Hb[(size_t)(k0 + r) * D + l0 + ll];
        }
        __syncthreads();
#pragma unroll 8
        for (int ll = 0; ll < 32; ll++) {
            float ra[8], rb[4];
#pragma unroll
            for (int a = 0; a < 8; a++) ra[a] = sA[tj + a * 16][ll];
#pragma unroll
            for (int c = 0; c < 4; c++) rb[c] = sB[tk + c * 16][ll];
#pragma unroll
            for (int a = 0; a < 8; a++)
#pragma unroll
                for (int c = 0; c < 4; c++) acc[a][c] += ra[a] * rb[c];
        }
        __syncthreads();
    }
    float* Eb = E + (size_t)b * N * N;
#pragma unroll
    for (int a = 0; a < 8; a++) {
        size_t ro = (size_t)(j0 + tj + a * 16) * N;
#pragma unroll
        for (int c = 0; c < 4; c++)
            Eb[ro + k0 + tk + c * 16] = acc[a][c];
    }
}

// ---------------------------------------------------------------------------
// T[b][k][j] = adj[b][j][k] > 0 ? E[b][j][k] + E[b][k][j] : NEG
// (transposed layout so the axis=1 softmax is a contiguous row softmax)
__global__ void __launch_bounds__(256) symmask_k(
    const float* __restrict__ E, const float* __restrict__ adj,
    float* __restrict__ T) {
    __shared__ float sE2[32][33];    // E[k][j]
    __shared__ float sE1t[32][33];   // E[j][k] transposed -> [k][j]
    __shared__ float sAdjt[32][33];  // adj[j][k] transposed -> [k][j]
    const int b = blockIdx.z;
    const int j0 = blockIdx.x * 32;
    const int k0 = blockIdx.y * 32;
    const float* Eb = E + (size_t)b * N * N;
    const float* Ab = adj + (size_t)b * N * N;
    float* Tb = T + (size_t)b * N * N;
    const int tid = threadIdx.x;
#pragma unroll
    for (int i = tid; i < 1024; i += 256) {
        int r = i >> 5, c = i & 31;
        sE2[r][c] = Eb[(size_t)(k0 + r) * N + j0 + c];
        sE1t[c][r] = Eb[(size_t)(j0 + r) * N + k0 + c];
        sAdjt[c][r] = Ab[(size_t)(j0 + r) * N + k0 + c];
    }
    __syncthreads();
#pragma unroll
    for (int i = tid; i < 1024; i += 256) {
        int kk = i >> 5, jj = i & 31;
        float v = (sAdjt[kk][jj] > 0.0f) ? (sE1t[kk][jj] + sE2[kk][jj]) : NEGV;
        Tb[(size_t)(k0 + kk) * N + j0 + jj] = v;
    }
}

// ---------------------------------------------------------------------------
// In-place row softmax over T rows (each row is one original column k).
__global__ void __launch_bounds__(256) softmax_k(float* __restrict__ T) {
    __shared__ float row[N];
    __shared__ float redm[8];
    __shared__ float reds[8];
    const int tid = threadIdx.x;
    const int lane = tid & 31, wid = tid >> 5;
    float* Tr = T + (size_t)blockIdx.x * N;

    float m = -3.4e38f;
    for (int i = tid; i < N; i += 256) {
        float v = Tr[i];
        row[i] = v;
        m = fmaxf(m, v);
    }
#pragma unroll
    for (int o = 16; o > 0; o >>= 1) m = fmaxf(m, __shfl_xor_sync(0xffffffffu, m, o));
    if (lane == 0) redm[wid] = m;
    __syncthreads();
    if (tid == 0) {
        float t = redm[0];
#pragma unroll
        for (int i = 1; i < 8; i++) t = fmaxf(t, redm[i]);
        redm[0] = t;
    }
    __syncthreads();
    m = redm[0];

    float s = 0.0f;
    for (int i = tid; i < N; i += 256) {
        float e = __expf(row[i] - m);   // masked (NEG) entries -> exactly 0
        row[i] = e;
        s += e;
    }
#pragma unroll
    for (int o = 16; o > 0; o >>= 1) s += __shfl_xor_sync(0xffffffffu, s, o);
    if (lane == 0) reds[wid] = s;
    __syncthreads();
    if (tid == 0) {
        float t = 0.0f;
#pragma unroll
        for (int i = 0; i < 8; i++) t += reds[i];
        reds[0] = t;
    }
    __syncthreads();
    const float inv = 1.0f / reds[0];
    for (int i = tid; i < N; i += 256) Tr[i] = row[i] * inv;
}

// ---------------------------------------------------------------------------
// hp[b][i][d] = relu( sum_j T[b][j][i] * h[b][j][d] )   (A^T * B GEMM)
// Tile: 64(i) x 128(d), K-step 32 over j.
__global__ void __launch_bounds__(256) hprime_k(
    const float* __restrict__ T, const float* __restrict__ h,
    float* __restrict__ hp) {
    __shared__ float sT[32][65];
    __shared__ float sH[32][129];
    const int b = blockIdx.y;
    const int i0 = blockIdx.x * 64;
    const int tid = threadIdx.x;
    const int ti = tid >> 4, td = tid & 15;
    const float* Tb = T + (size_t)b * N * N;
    const float* Hb = h + (size_t)b * N * D;
    float acc[4][8];
#pragma unroll
    for (int a = 0; a < 4; a++)
#pragma unroll
        for (int c = 0; c < 8; c++) acc[a][c] = 0.0f;

    for (int j0 = 0; j0 < N; j0 += 32) {
#pragma unroll
        for (int i = tid; i < 32 * 64; i += 256) {
            int jj = i >> 6, ii = i & 63;
            sT[jj][ii] = Tb[(size_t)(j0 + jj) * N + i0 + ii];
        }
#pragma unroll
        for (int i = tid; i < 32 * 128; i += 256) {
            int jj = i >> 7, dd = i & 127;
            sH[jj][dd] = Hb[(size_t)(j0 + jj) * D + dd];
        }
        __syncthreads();
#pragma unroll 8
        for (int jj = 0; jj < 32; jj++) {
            float ra[4], rb[8];
#pragma unroll
            for (int a = 0; a < 4; a++) ra[a] = sT[jj][ti + a * 16];
#pragma unroll
            for (int c = 0; c < 8; c++) rb[c] = sH[jj][td + c * 16];
#pragma unroll
            for (int a = 0; a < 4; a++)
#pragma unroll
                for (int c = 0; c < 8; c++) acc[a][c] += ra[a] * rb[c];
        }
        __syncthreads();
    }
#pragma unroll
    for (int a = 0; a < 4; a++) {
        size_t ro = ((size_t)b * N + i0 + ti + a * 16) * D;
#pragma unroll
        for (int c = 0; c < 8; c++)
            hp[ro + td + c * 16] = fmaxf(acc[a][c], 0.0f);
    }
}

// ---------------------------------------------------------------------------
// Gate + output.  One warp per row.
__global__ void __launch_bounds__(256) gate_k(
    const float* __restrict__ x, const float* __restrict__ hp,
    const float* __restrict__ gw, const float* __restrict__ gb,
    float* __restrict__ out) {
    const int lane = threadIdx.x & 31;
    const size_t row = (size_t)blockIdx.x * 8 + (threadIdx.x >> 5);
    const float4 xv = reinterpret_cast<const float4*>(x + row * D)[lane];
    const float4 hv = reinterpret_cast<const float4*>(hp + row * D)[lane];
    const float4 g1 = reinterpret_cast<const float4*>(gw)[lane];
    const float4 g2 = reinterpret_cast<const float4*>(gw + D)[lane];
    float p = xv.x * g1.x + xv.y * g1.y + xv.z * g1.z + xv.w * g1.w
            + hv.x * g2.x + hv.y * g2.y + hv.z * g2.z + hv.w * g2.w;
#pragma unroll
    for (int o = 16; o > 0; o >>= 1) p += __shfl_xor_sync(0xffffffffu, p, o);
    const float c = 1.0f / (1.0f + __expf(-(p + gb[0])));
    const float d1 = 1.0f - c;
    float4 o4;
    o4.x = c * xv.x + d1 * hv.x;
    o4.y = c * xv.y + d1 * hv.y;
    o4.z = c * xv.z + d1 * hv.z;
    o4.w = c * xv.w + d1 * hv.w;
    reinterpret_cast<float4*>(out + row * D)[lane] = o4;
}

// ---------------------------------------------------------------------------
extern "C" void kernel_launch(void* const* d_in, const int* in_sizes, int n_in,
                              void* d_out, int out_size) {
    const float* x   = (const float*)d_in[0];
    const float* adj = (const float*)d_in[1];
    const float* W_w = (const float*)d_in[2];
    const float* W_b = (const float*)d_in[3];
    const float* A   = (const float*)d_in[4];
    const float* gw  = (const float*)d_in[5];
    const float* gb  = (const float*)d_in[6];
    float* out = (float*)d_out;

    float *pWt, *ph, *phA, *php, *pE, *pT;
    cudaGetSymbolAddress((void**)&pWt, g_Wt);
    cudaGetSymbolAddress((void**)&ph,  g_h);
    cudaGetSymbolAddress((void**)&phA, g_hA);
    cudaGetSymbolAddress((void**)&php, g_hp);
    cudaGetSymbolAddress((void**)&pE,  g_E);
    cudaGetSymbolAddress((void**)&pT,  g_T);

    transpose_k<<<dim3(4, 4), dim3(32, 8)>>>(W_w, pWt);
    gemm_rows_k<<<(B * N) / 32, 256>>>(x, pWt, W_b, ph);
    gemm_rows_k<<<(B * N) / 32, 256>>>(ph, A, nullptr, phA);
    e_gemm_k<<<dim3(N / 64, N / 128, B), 256>>>(phA, ph, pE);
    symmask_k<<<dim3(N / 32, N / 32, B), 256>>>(pE, adj, pT);
    softmax_k<<<B * N, 256>>>(pT);
    hprime_k<<<dim3(N / 64, B), 256>>>(pT, ph, php);
    gate_k<<<(B * N) / 8, 256>>>(x, php, gw, gb, out);
}